// round 13
// baseline (speedup 1.0000x reference)
#include <cuda_runtime.h>
#include <cuda_bf16.h>
#include <math.h>
#include <stdint.h>

#define NPIX (16*96*16384)
#define GN_N 393216

// ---------------- scratch ----------------------------------------------------
__device__ float g_buf1[NPIX];
__device__ float g_buf2[NPIX];
__device__ float g_buf3[NPIX];
__device__ float g_buf4[NPIX];
__device__ float g_qkv[3*NPIX];
__device__ float g_part0[16384];
__device__ float g_part1[1024];
__device__ float g_part2[16384];
__device__ float g_stats[3*64*2];
__device__ float g_film[16*192];
// conv weights: Winograd U, phase-ordered [p*3+ky][96 co][48 k2]
__device__ uint32_t g_w1hi[55296], g_w1lo[55296];
__device__ uint32_t g_w2hi[55296], g_w2lo[55296];
__device__ uint32_t g_qwhi[13824], g_qwlo[13824];
__device__ uint32_t g_pwhi[4608],  g_pwlo[4608];

// ---------------- helpers ----------------------------------------------------
__device__ __forceinline__ uint32_t smem_u32(const void* p) {
    uint32_t a;
    asm("{ .reg .u64 t; cvta.to.shared.u64 t, %1; cvt.u32.u64 %0, t; }"
        : "=r"(a) : "l"(p));
    return a;
}
__device__ __forceinline__ void mma16816(float* c, const uint32_t* a,
                                         const uint32_t* b) {
    asm volatile(
        "mma.sync.aligned.m16n8k16.row.col.f32.bf16.bf16.f32 "
        "{%0,%1,%2,%3}, {%4,%5,%6,%7}, {%8,%9}, {%0,%1,%2,%3};"
        : "+f"(c[0]), "+f"(c[1]), "+f"(c[2]), "+f"(c[3])
        : "r"(a[0]), "r"(a[1]), "r"(a[2]), "r"(a[3]), "r"(b[0]), "r"(b[1]));
}
__device__ __forceinline__ void ldsm4(uint32_t* r, uint32_t a) {
    asm volatile("ldmatrix.sync.aligned.m8n8.x4.shared.b16 {%0,%1,%2,%3}, [%4];"
        : "=r"(r[0]), "=r"(r[1]), "=r"(r[2]), "=r"(r[3]) : "r"(a));
}
__device__ __forceinline__ void bsplit(float v, unsigned short& h,
                                       unsigned short& l) {
    __nv_bfloat16 hv = __float2bfloat16(v);
    __nv_bfloat16 lv = __float2bfloat16(v - __bfloat162float(hv));
    h = __bfloat16_as_ushort(hv);
    l = __bfloat16_as_ushort(lv);
}
__device__ __forceinline__ void cpa16(uint32_t s, const void* g) {
    asm volatile("cp.async.ca.shared.global [%0], [%1], 16;"
                 :: "r"(s), "l"(g) : "memory");
}
#define CP_COMMIT() asm volatile("cp.async.commit_group;" ::: "memory")
#define CP_WAIT0()  asm volatile("cp.async.wait_group 0;" ::: "memory")
#define CP_WAIT1()  asm volatile("cp.async.wait_group 1;" ::: "memory")

// ---------------- weight prepack ---------------------------------------------
// is33: Winograd U, phase-ordered: i = (p*3+ky)*4608 + co*48 + k2
__global__ __launch_bounds__(256) void prep_k(
    const float* __restrict__ wsrc, uint32_t* __restrict__ dh,
    uint32_t* __restrict__ dl, int n, int is33)
{
    int i = blockIdx.x*256 + threadIdx.x;
    if (i >= n) return;
    float v0, v1;
    if (is33) {
        int ip = i / 4608, r = i - ip*4608;
        int p = ip / 3, ky = ip - p*3;
        int co = r / 48, k2 = r - co*48, ci = k2 << 1;
        float a0 = wsrc[(co*96 + ci)*9 + ky*3 + 0];
        float a1 = wsrc[(co*96 + ci)*9 + ky*3 + 1];
        float a2 = wsrc[(co*96 + ci)*9 + ky*3 + 2];
        float b0 = wsrc[(co*96 + ci + 1)*9 + ky*3 + 0];
        float b1 = wsrc[(co*96 + ci + 1)*9 + ky*3 + 1];
        float b2 = wsrc[(co*96 + ci + 1)*9 + ky*3 + 2];
        v0 = (p == 0) ? a0 : (p == 1) ? 0.5f*(a0+a1+a2)
           : (p == 2) ? 0.5f*(a0-a1+a2) : a2;
        v1 = (p == 0) ? b0 : (p == 1) ? 0.5f*(b0+b1+b2)
           : (p == 2) ? 0.5f*(b0-b1+b2) : b2;
    } else {
        int co = i / 48, k2 = i - co*48, ci = k2 << 1;
        v0 = wsrc[co*96 + ci];
        v1 = wsrc[co*96 + ci + 1];
    }
    unsigned short h0, l0, h1, l1;
    bsplit(v0, h0, l0);
    bsplit(v1, h1, l1);
    dh[i] = (uint32_t)h0 | ((uint32_t)h1 << 16);
    dl[i] = (uint32_t)l0 | ((uint32_t)l1 << 16);
}

// ---------------- conv3x3: 1D Winograd F(2,3), p-outer, 2 CTAs/SM ------------
// V single slot [64 t][104 ci] u16 x2; U double-buffered via cp.async.
#define PS  104
#define PS2 208
#define WV_H  0                      // 13,312 B
#define WV_L  13312                  // 13,312 B
#define WU    26624                  // 2 bufs x 39,936 (hi 19,968 + lo 19,968)
#define WBIAS 106496
#define WINO_SMEM 106880

__global__ __launch_bounds__(256) void conv3x3_wino_k(
    const float* __restrict__ in, const uint32_t* __restrict__ uphi,
    const uint32_t* __restrict__ uplo,
    const float* __restrict__ bias, float* __restrict__ out,
    float* __restrict__ part)
{
    extern __shared__ char smem[];
    uint32_t sb = smem_u32(smem);
    unsigned short* sVh = (unsigned short*)(smem + WV_H);
    unsigned short* sVl = (unsigned short*)(smem + WV_L);
    float* sbias = (float*)(smem + WBIAS);

    int tid = threadIdx.x, wid = tid >> 5, lane = tid & 31;
    int gid = lane >> 2, tig = lane & 3;
    int h = blockIdx.x, b = blockIdx.y;
    int m0 = (wid & 3) * 16;          // t-tile base
    int n0 = (wid >> 2) * 48;         // co base

    float acc[24], y0[24], y1[24];
#pragma unroll
    for (int r = 0; r < 24; r++) { acc[r] = 0.f; y0[r] = 0.f; y1[r] = 0.f; }

    for (int i = tid; i < 96; i += 256) sbias[i] = bias[i];

    uint32_t aH = sb + WV_H + (uint32_t)((((m0 + (lane & 15))*PS) + ((lane >> 4) << 3)) << 1);
    uint32_t aL = aH + (WV_L - WV_H);

    // prologue: prefetch U(phase 0) into buf 0
    for (int i4 = tid; i4 < 1152; i4 += 256) {
        int co = i4 / 12, k2 = (i4 - co*12) << 2;
        uint32_t so = (uint32_t)((co*52 + k2) << 2);
        cpa16(sb + WU + so,         uphi + co*48 + k2);
        cpa16(sb + WU + 19968 + so, uplo + co*48 + k2);
    }
    CP_COMMIT();

#pragma unroll
    for (int p = 0; p < 4; p++) {
        for (int ky = 0; ky < 3; ky++) {
            int phase = p*3 + ky;
            int gh = h + ky - 1;
            __syncthreads();               // prev MMA done with V slot + U buf
            // build V_p(ky) directly from global (L2-resident rows)
            for (int i = tid; i < 6144; i += 256) {
                int t = i & 63, ci = i >> 6;
                float d0 = 0.f, d1 = 0.f, d2 = 0.f, d3 = 0.f;
                if ((unsigned)gh < 128u) {
                    const float* row = in + (((size_t)(b*96 + ci)) << 14) + (gh << 7);
                    int c = t << 1;
                    float2 m = *(const float2*)(row + c);
                    d1 = m.x; d2 = m.y;
                    if (t > 0)  d0 = row[c - 1];
                    if (t < 63) d3 = row[c + 2];
                }
                float v = (p == 0) ? d0 - d2 : (p == 1) ? d1 + d2
                        : (p == 2) ? d2 - d1 : d1 - d3;
                unsigned short hv, lv;
                bsplit(v, hv, lv);
                sVh[t*PS + ci] = hv;
                sVl[t*PS + ci] = lv;
            }
            // prefetch U(phase+1) into the other buffer
            if (phase < 11) {
                int pn = phase + 1;
                uint32_t ub = sb + WU + (uint32_t)((pn & 1) * 39936);
                const uint32_t* ph = uphi + pn*4608;
                const uint32_t* pl = uplo + pn*4608;
                for (int i4 = tid; i4 < 1152; i4 += 256) {
                    int co = i4 / 12, k2 = (i4 - co*12) << 2;
                    uint32_t so = (uint32_t)((co*52 + k2) << 2);
                    cpa16(ub + so,         ph + co*48 + k2);
                    cpa16(ub + 19968 + so, pl + co*48 + k2);
                }
                CP_COMMIT();
                CP_WAIT1();                // U(phase) complete
            } else {
                CP_WAIT0();
            }
            __syncthreads();               // V + U visible

            uint32_t* sUh = (uint32_t*)(smem + WU + (phase & 1)*39936);
            uint32_t* sUl = sUh + 4992;
#pragma unroll
            for (int kc = 0; kc < 6; kc++) {
                uint32_t ahi[4], alo[4];
                ldsm4(ahi, aH + kc*32);
                ldsm4(alo, aL + kc*32);
#pragma unroll
                for (int nt = 0; nt < 6; nt++) {
                    int co = n0 + nt*8 + gid;
                    int k2 = (kc << 3) + tig;
                    uint32_t bh[2], bl[2];
                    bh[0] = sUh[co*52 + k2];
                    bh[1] = sUh[co*52 + k2 + 4];
                    bl[0] = sUl[co*52 + k2];
                    bl[1] = sUl[co*52 + k2 + 4];
                    float* c = acc + nt*4;
                    mma16816(c, ahi, bh);
                    mma16816(c, ahi, bl);
                    mma16816(c, alo, bh);
                }
            }
        }
        // fold m_p into y0/y1 (y0 = m0+m1+m2, y1 = m1-m2-m3)
#pragma unroll
        for (int r = 0; r < 24; r++) {
            if (p == 0)      { y0[r] = acc[r]; }
            else if (p == 1) { y0[r] += acc[r]; y1[r] = acc[r]; }
            else if (p == 2) { y0[r] += acc[r]; y1[r] -= acc[r]; }
            else             { y1[r] -= acc[r]; }
            acc[r] = 0.f;
        }
    }

    // epilogue: bias, float2 stores, GN partials
    __syncthreads();
    size_t obase = (((size_t)(b*96)) << 14) + (h << 7);
    float gs[2] = {0.f, 0.f}, gq[2] = {0.f, 0.f};
    int t0 = m0 + gid, t1 = t0 + 8;
#pragma unroll
    for (int nt = 0; nt < 6; nt++) {
        int co = n0 + nt*8 + (tig << 1);
        float bs0 = sbias[co], bs1 = sbias[co + 1];
        int lg = nt / 3;
#pragma unroll
        for (int r = 0; r < 4; r++) {
            float bsv = (r & 1) ? bs1 : bs0;
            float v0 = y0[nt*4 + r] + bsv;
            float v1 = y1[nt*4 + r] + bsv;
            int tcur = (r < 2) ? t0 : t1;
            int cocur = co + (r & 1);
            float2 st = {v0, v1};
            *(float2*)&out[obase + (((size_t)cocur) << 14) + (tcur << 1)] = st;
            gs[lg] += v0 + v1;
            gq[lg] += v0*v0 + v1*v1;
        }
    }
    __syncthreads();                       // U area free for reuse
    float* redS = (float*)(smem + WU);     // [4][256]
    float* redQ = redS + 1024;
    int gb = (wid >> 2) * 2;
#pragma unroll
    for (int g = 0; g < 4; g++) {
        redS[g*256 + tid] = (g == gb) ? gs[0] : ((g == gb+1) ? gs[1] : 0.f);
        redQ[g*256 + tid] = (g == gb) ? gq[0] : ((g == gb+1) ? gq[1] : 0.f);
    }
    __syncthreads();
    for (int st = 128; st > 0; st >>= 1) {
        if (tid < st) {
#pragma unroll
            for (int g = 0; g < 4; g++) {
                redS[g*256 + tid] += redS[g*256 + tid + st];
                redQ[g*256 + tid] += redQ[g*256 + tid + st];
            }
        }
        __syncthreads();
    }
    if (tid < 4) {
        part[(b*4 + tid)*128 + h]        = redS[tid*256];
        part[8192 + (b*4 + tid)*128 + h] = redQ[tid*256];
    }
}

// ---------------- qkv 1x1 via mma.sync + ldmatrix (GN2 fused) — R10 ----------
#define Q_AH   0
#define Q_AL   26624
#define Q_BH   53248
#define Q_BL   73216
#define Q_BIAS 93184
#define QKV_SMEM (93184 + 384)

__global__ __launch_bounds__(256) void qkv_mma_k(
    const float* __restrict__ R, const float* __restrict__ stats,
    const float* __restrict__ ga, const float* __restrict__ ba,
    const uint32_t* __restrict__ qwhi, const uint32_t* __restrict__ qwlo,
    const float* __restrict__ qb, float* __restrict__ out)
{
    extern __shared__ char smem[];
    uint32_t sb = smem_u32(smem);
    unsigned short* sAh = (unsigned short*)(smem + Q_AH);
    unsigned short* sAl = (unsigned short*)(smem + Q_AL);
    uint32_t* sBhi = (uint32_t*)(smem + Q_BH);
    uint32_t* sBlo = (uint32_t*)(smem + Q_BL);
    float*    sbias = (float*)(smem + Q_BIAS);

    int tid = threadIdx.x, wid = tid >> 5, lane = tid & 31;
    int gid = lane >> 2, tig = lane & 3;
    int h = blockIdx.x, cog = blockIdx.y, b = blockIdx.z;
    int m0 = (wid & 3) * 32;
    int n0 = (wid >> 2) * 48;

    float acc[12][4];
#pragma unroll
    for (int t = 0; t < 12; t++)
#pragma unroll
        for (int r = 0; r < 4; r++) acc[t][r] = 0.f;

    for (int i = tid; i < 12288; i += 256) {
        int ci = i >> 7, col = i & 127;
        int bg = b*4 + ci/24;
        float v = R[(((size_t)(b*96 + ci)) << 14) + (h << 7) + col];
        float xn = (v - stats[bg*2])*stats[bg*2+1]*ga[ci] + ba[ci];
        unsigned short hv, lv;
        bsplit(xn, hv, lv);
        int a = col*PS + ci;
        sAh[a] = hv;
        sAl[a] = lv;
    }
    for (int i4 = tid; i4 < 1152; i4 += 256) {
        int co = i4 / 12, k2 = (i4 - co*12) << 2;
        uint4 vh = *(const uint4*)&qwhi[cog*4608 + co*48 + k2];
        uint4 vl = *(const uint4*)&qwlo[cog*4608 + co*48 + k2];
        *(uint4*)&sBhi[co*52 + k2] = vh;
        *(uint4*)&sBlo[co*52 + k2] = vl;
    }
    for (int i = tid; i < 96; i += 256) sbias[i] = qb[cog*96 + i];
    __syncthreads();

    uint32_t aH = sb + Q_AH + (uint32_t)((((m0 + (lane & 15))*PS) + ((lane >> 4) << 3)) << 1);
    uint32_t aL = aH + (Q_AL - Q_AH);

#pragma unroll
    for (int kc = 0; kc < 6; kc++) {
        uint32_t ahi[8], alo[8];
        ldsm4(ahi,     aH + kc*32);
        ldsm4(ahi + 4, aH + 16*PS2 + kc*32);
        ldsm4(alo,     aL + kc*32);
        ldsm4(alo + 4, aL + 16*PS2 + kc*32);
        uint32_t bhi[12], blo[12];
#pragma unroll
        for (int nt = 0; nt < 6; nt++) {
            int co = n0 + nt*8 + gid;
            int k2 = (kc << 3) + tig;
            bhi[nt*2]   = sBhi[co*52 + k2];
            bhi[nt*2+1] = sBhi[co*52 + k2 + 4];
            blo[nt*2]   = sBlo[co*52 + k2];
            blo[nt*2+1] = sBlo[co*52 + k2 + 4];
        }
#pragma unroll
        for (int mt = 0; mt < 2; mt++)
#pragma unroll
            for (int nt = 0; nt < 6; nt++) {
                float* c = acc[mt*6 + nt];
                mma16816(c, &ahi[mt*4], &bhi[nt*2]);
                mma16816(c, &ahi[mt*4], &blo[nt*2]);
                mma16816(c, &alo[mt*4], &bhi[nt*2]);
            }
    }

    size_t obase = (((size_t)(b*288 + cog*96)) << 14) + (h << 7);
#pragma unroll
    for (int mt = 0; mt < 2; mt++) {
        int p = m0 + mt*16 + gid;
#pragma unroll
        for (int nt = 0; nt < 6; nt++) {
            int co = n0 + nt*8 + (tig << 1);
            float* c = acc[mt*6 + nt];
            float bs0 = sbias[co], bs1 = sbias[co+1];
            out[obase + (((size_t)co)   << 14) + p]     = c[0] + bs0;
            out[obase + (((size_t)co+1) << 14) + p]     = c[1] + bs1;
            out[obase + (((size_t)co)   << 14) + p + 8] = c[2] + bs0;
            out[obase + (((size_t)co+1) << 14) + p + 8] = c[3] + bs1;
        }
    }
}

// ---------------- proj 1x1 via mma.sync + ldmatrix + residual — R10 ----------
__global__ __launch_bounds__(256) void proj_mma_k(
    const float* __restrict__ o0, const float* __restrict__ o1,
    const float* __restrict__ R,
    const uint32_t* __restrict__ pwhi, const uint32_t* __restrict__ pwlo,
    const float* __restrict__ pb, float* __restrict__ A)
{
    extern __shared__ char smem[];
    uint32_t sb = smem_u32(smem);
    unsigned short* sAh = (unsigned short*)(smem + Q_AH);
    unsigned short* sAl = (unsigned short*)(smem + Q_AL);
    uint32_t* sBhi = (uint32_t*)(smem + Q_BH);
    uint32_t* sBlo = (uint32_t*)(smem + Q_BL);
    float*    sbias = (float*)(smem + Q_BIAS);

    int tid = threadIdx.x, wid = tid >> 5, lane = tid & 31;
    int gid = lane >> 2, tig = lane & 3;
    int h = blockIdx.x, b = blockIdx.y;
    int m0 = (wid & 3) * 32;
    int n0 = (wid >> 2) * 48;

    float acc[12][4];
#pragma unroll
    for (int t = 0; t < 12; t++)
#pragma unroll
        for (int r = 0; r < 4; r++) acc[t][r] = 0.f;

    for (int i = tid; i < 12288; i += 256) {
        int ci = i >> 7, col = i & 127;
        size_t idx = (((size_t)(b*96 + ci)) << 14) + (h << 7) + col;
        float v = o0[idx] + o1[idx];
        unsigned short hv, lv;
        bsplit(v, hv, lv);
        int a = col*PS + ci;
        sAh[a] = hv;
        sAl[a] = lv;
    }
    for (int i4 = tid; i4 < 1152; i4 += 256) {
        int co = i4 / 12, k2 = (i4 - co*12) << 2;
        uint4 vh = *(const uint4*)&pwhi[co*48 + k2];
        uint4 vl = *(const uint4*)&pwlo[co*48 + k2];
        *(uint4*)&sBhi[co*52 + k2] = vh;
        *(uint4*)&sBlo[co*52 + k2] = vl;
    }
    for (int i = tid; i < 96; i += 256) sbias[i] = pb[i];
    __syncthreads();

    uint32_t aH = sb + Q_AH + (uint32_t)((((m0 + (lane & 15))*PS) + ((lane >> 4) << 3)) << 1);
    uint32_t aL = aH + (Q_AL - Q_AH);

#pragma unroll
    for (int kc = 0; kc < 6; kc++) {
        uint32_t ahi[8], alo[8];
        ldsm4(ahi,     aH + kc*32);
        ldsm4(ahi + 4, aH + 16*PS2 + kc*32);
        ldsm4(alo,     aL + kc*32);
        ldsm4(alo + 4, aL + 16*PS2 + kc*32);
        uint32_t bhi[12], blo[12];
#pragma unroll
        for (int nt = 0; nt < 6; nt++) {
            int co = n0 + nt*8 + gid;
            int k2 = (kc << 3) + tig;
            bhi[nt*2]   = sBhi[co*52 + k2];
            bhi[nt*2+1] = sBhi[co*52 + k2 + 4];
            blo[nt*2]   = sBlo[co*52 + k2];
            blo[nt*2+1] = sBlo[co*52 + k2 + 4];
        }
#pragma unroll
        for (int mt = 0; mt < 2; mt++)
#pragma unroll
            for (int nt = 0; nt < 6; nt++) {
                float* c = acc[mt*6 + nt];
                mma16816(c, &ahi[mt*4], &bhi[nt*2]);
                mma16816(c, &ahi[mt*4], &blo[nt*2]);
                mma16816(c, &alo[mt*4], &bhi[nt*2]);
            }
    }

    size_t obase = (((size_t)(b*96)) << 14) + (h << 7);
#pragma unroll
    for (int mt = 0; mt < 2; mt++) {
        int p = m0 + mt*16 + gid;
#pragma unroll
        for (int nt = 0; nt < 6; nt++) {
            int co = n0 + nt*8 + (tig << 1);
            float* c = acc[mt*6 + nt];
            float bs0 = sbias[co], bs1 = sbias[co+1];
            size_t i00 = obase + (((size_t)co) << 14) + p;
            size_t i10 = obase + (((size_t)co+1) << 14) + p;
            A[i00]     = R[i00]     + 0.5f*c[0] + bs0;
            A[i10]     = R[i10]     + 0.5f*c[1] + bs1;
            A[i00 + 8] = R[i00 + 8] + 0.5f*c[2] + bs0;
            A[i10 + 8] = R[i10 + 8] + 0.5f*c[3] + bs1;
        }
    }
}

// ---------------- GN finalize ------------------------------------------------
__global__ void gn_finalize_k(const float* __restrict__ part, int nch, int sqoff,
                              float* __restrict__ stats)
{
    int bg = threadIdx.x;
    float s = 0, q = 0;
    for (int c = 0; c < nch; c++) {
        s += part[bg*nch + c];
        q += part[sqoff + bg*nch + c];
    }
    float mean = s * (1.f/393216.f);
    float var  = q * (1.f/393216.f) - mean*mean;
    stats[bg*2 + 0] = mean;
    stats[bg*2 + 1] = rsqrtf(var + 1e-5f);
}

// ---------------- time-embedding MLP -----------------------------------------
__global__ void temb_k(const float* __restrict__ te, const float* __restrict__ wt,
                       const float* __restrict__ bt, float* __restrict__ film)
{
    __shared__ float sh[256];
    int b = blockIdx.x, j = blockIdx.y*32 + threadIdx.x;
    for (int i = threadIdx.x; i < 256; i += 32) sh[i] = te[b*256 + i];
    __syncthreads();
    const float* wr = wt + j*256;
    float s = bt[j];
#pragma unroll 4
    for (int k = 0; k < 256; k++) s += sh[k]*wr[k];
    s = s / (1.f + expf(-s));
    film[b*192 + j] = s;
}

// ---------------- apply GN1+SiLU+FiLM, emit GN2 partials ---------------------
__global__ __launch_bounds__(256) void apply1_k(
    const float* __restrict__ x, const float* __restrict__ stats,
    const float* __restrict__ g1, const float* __restrict__ be1,
    const float* __restrict__ film, float* __restrict__ out,
    float* __restrict__ part)
{
    int bg = blockIdx.x, chunk = blockIdx.y;
    int b = bg >> 2, g = bg & 3;
    int tid = threadIdx.x;
    size_t base = (size_t)bg*GN_N + (size_t)chunk*49152;
    float mean = stats[bg*2], rstd = stats[bg*2+1];
    const float4* xp = (const float4*)(x + base);
    float4* op = (float4*)(out + base);

    float sx=0, sy=0, sz=0, sw=0, qx=0, qy=0, qz=0, qw=0;
    for (int i = tid; i < 12288; i += 256) {
        int c = g*24 + chunk*3 + (i >> 12);
        float gam = g1[c]*rstd;
        float bet = be1[c] - mean*gam;
        float shf = 1.f + film[b*192 + c];
        float bia = film[b*192 + 96 + c];
        float4 v = xp[i];
        float t;
        t = v.x*gam + bet; t = t/(1.f+expf(-t)); v.x = t*shf + bia;
        t = v.y*gam + bet; t = t/(1.f+expf(-t)); v.y = t*shf + bia;
        t = v.z*gam + bet; t = t/(1.f+expf(-t)); v.z = t*shf + bia;
        t = v.w*gam + bet; t = t/(1.f+expf(-t)); v.w = t*shf + bia;
        op[i] = v;
        sx += v.x; sy += v.y; sz += v.z; sw += v.w;
        qx += v.x*v.x; qy += v.y*v.y; qz += v.z*v.z; qw += v.w*v.w;
    }
    __shared__ double sh[512];
    sh[tid]       = (double)sx + sy + sz + sw;
    sh[256 + tid] = (double)qx + qy + qz + qw;
    __syncthreads();
    for (int st = 128; st > 0; st >>= 1) {
        if (tid < st) { sh[tid] += sh[tid+st]; sh[256+tid] += sh[256+tid+st]; }
        __syncthreads();
    }
    if (tid == 0) {
        part[bg*8 + chunk]       = (float)sh[0];
        part[512 + bg*8 + chunk] = (float)sh[256];
    }
}

// ---------------- final: SiLU(GN(conv2)) -> d_out ----------------------------
__global__ __launch_bounds__(256) void apply3_k(
    const float* __restrict__ x, const float* __restrict__ stats,
    const float* __restrict__ g2, const float* __restrict__ be2,
    float* __restrict__ out)
{
    int idx4 = blockIdx.x*256 + threadIdx.x;
    if (idx4 >= NPIX/4) return;
    int flat = idx4 << 2;
    int cimg = flat >> 14;
    int b = cimg / 96, c = cimg - 96*b;
    int bg = b*4 + c/24;
    float mean = stats[bg*2], rstd = stats[bg*2+1];
    float gam = g2[c]*rstd;
    float bet = be2[c] - mean*gam;
    float4 v = *(const float4*)&x[flat];
    float t;
    t = v.x*gam + bet; v.x = t/(1.f+expf(-t));
    t = v.y*gam + bet; v.y = t/(1.f+expf(-t));
    t = v.z*gam + bet; v.z = t/(1.f+expf(-t));
    t = v.w*gam + bet; v.w = t/(1.f+expf(-t));
    *(float4*)&out[flat] = v;
}

// ---------------- attention core ---------------------------------------------
__global__ __launch_bounds__(256) void attn_core_k(
    const float* __restrict__ qkv, float* __restrict__ o0, float* __restrict__ o1)
{
    extern __shared__ float sm[];
    float* sq   = sm;
    float* slog = sq + 18432;
    float* spr  = slog + 576;

    int b = blockIdx.y, branch = blockIdx.z;
    int hn = blockIdx.x >> 4, wn = blockIdx.x & 15;
    int sh = branch*4;
    int h0 = hn*8 + sh, w0 = wn*8 + sh;
    int tid = threadIdx.x;

    for (int i = tid; i < 4608; i += 256) {
        int c = i >> 4, lq = i & 15, l = lq << 2;
        int gh = (h0 + (l >> 3)) & 127, gw = (w0 + (l & 7)) & 127;
        *(float4*)&sq[(c << 6) + l] =
            *(const float4*)&qkv[(((size_t)(b*288 + c)) << 14) + (gh << 7) + gw];
    }
    __syncthreads();

    const float scale = 0.40824829046386307f;
    for (int i = tid; i < 576; i += 256) {
        int head = i / 36, r = i - head*36, d = r / 6, e = r - d*6;
        const float* qp = &sq[(head*6 + d) << 6];
        const float* kp = &sq[(96 + head*6 + e) << 6];
        float a = 0.f;
#pragma unroll 8
        for (int l = 0; l < 64; l++) a += qp[l]*kp[l];
        slog[i] = a*scale;
    }
    __syncthreads();

    if (tid < 96) {
        int head = tid / 6, d = tid - head*6, base = head*36 + d*6;
        float m = -1e30f;
#pragma unroll
        for (int e = 0; e < 6; e++) m = fmaxf(m, slog[base+e]);
        float ex[6]; float s = 0.f;
#pragma unroll
        for (int e = 0; e < 6; e++) { ex[e] = expf(slog[base+e] - m); s += ex[e]; }
        float inv = 1.f/s;
#pragma unroll
        for (int e = 0; e < 6; e++) spr[base+e] = ex[e]*inv;
    }
    __syncthreads();

    float* o = branch ? o1 : o0;
    for (int i = tid; i < 1536; i += 256) {
        int ch = i >> 4, lq = i & 15, l = lq << 2;
        int head = ch / 6, d = ch - head*6;
        float4 a = {0.f, 0.f, 0.f, 0.f};
#pragma unroll
        for (int e = 0; e < 6; e++) {
            float p = spr[head*36 + d*6 + e];
            float4 vv = *(const float4*)&sq[((192 + head*6 + e) << 6) + l];
            a.x += p*vv.x; a.y += p*vv.y; a.z += p*vv.z; a.w += p*vv.w;
        }
        int gh = (h0 + (l >> 3)) & 127, gw = (w0 + (l & 7)) & 127;
        *(float4*)&o[(((size_t)(b*96 + ch)) << 14) + (gh << 7) + gw] = a;
    }
}

// ---------------- launch -----------------------------------------------------
extern "C" void kernel_launch(void* const* d_in, const int* in_sizes, int n_in,
                              void* d_out, int out_size)
{
    const float* x      = (const float*)d_in[0];
    const float* t_emb  = (const float*)d_in[1];
    const float* w1     = (const float*)d_in[2];
    const float* b1     = (const float*)d_in[3];
    const float* g1     = (const float*)d_in[4];
    const float* be1    = (const float*)d_in[5];
    const float* wt     = (const float*)d_in[6];
    const float* bt     = (const float*)d_in[7];
    const float* qkv_w  = (const float*)d_in[8];
    const float* qkv_b  = (const float*)d_in[9];
    const float* proj_w = (const float*)d_in[10];
    const float* proj_b = (const float*)d_in[11];
    const float* ga     = (const float*)d_in[12];
    const float* ba     = (const float*)d_in[13];
    const float* w2     = (const float*)d_in[14];
    const float* b2     = (const float*)d_in[15];
    const float* g2     = (const float*)d_in[16];
    const float* be2    = (const float*)d_in[17];
    float* out = (float*)d_out;

    float *buf1, *buf2, *buf3, *buf4, *qkvb, *part0, *part1, *part2, *stats, *film;
    uint32_t *w1hi, *w1lo, *w2hi, *w2lo, *qwhi, *qwlo, *pwhi, *pwlo;
    cudaGetSymbolAddress((void**)&buf1, g_buf1);
    cudaGetSymbolAddress((void**)&buf2, g_buf2);
    cudaGetSymbolAddress((void**)&buf3, g_buf3);
    cudaGetSymbolAddress((void**)&buf4, g_buf4);
    cudaGetSymbolAddress((void**)&qkvb, g_qkv);
    cudaGetSymbolAddress((void**)&part0, g_part0);
    cudaGetSymbolAddress((void**)&part1, g_part1);
    cudaGetSymbolAddress((void**)&part2, g_part2);
    cudaGetSymbolAddress((void**)&stats, g_stats);
    cudaGetSymbolAddress((void**)&film, g_film);
    cudaGetSymbolAddress((void**)&w1hi, g_w1hi);
    cudaGetSymbolAddress((void**)&w1lo, g_w1lo);
    cudaGetSymbolAddress((void**)&w2hi, g_w2hi);
    cudaGetSymbolAddress((void**)&w2lo, g_w2lo);
    cudaGetSymbolAddress((void**)&qwhi, g_qwhi);
    cudaGetSymbolAddress((void**)&qwlo, g_qwlo);
    cudaGetSymbolAddress((void**)&pwhi, g_pwhi);
    cudaGetSymbolAddress((void**)&pwlo, g_pwlo);

    const int ATTN_SMEM = (18432 + 576 + 576) * 4;
    cudaFuncSetAttribute(attn_core_k, cudaFuncAttributeMaxDynamicSharedMemorySize,
                         ATTN_SMEM);
    cudaFuncSetAttribute(conv3x3_wino_k, cudaFuncAttributeMaxDynamicSharedMemorySize,
                         WINO_SMEM);
    cudaFuncSetAttribute(qkv_mma_k, cudaFuncAttributeMaxDynamicSharedMemorySize,
                         QKV_SMEM);
    cudaFuncSetAttribute(proj_mma_k, cudaFuncAttributeMaxDynamicSharedMemorySize,
                         QKV_SMEM);

    dim3 cgrid(128, 16);

    prep_k<<<216, 256>>>(w1, w1hi, w1lo, 55296, 1);
    prep_k<<<216, 256>>>(w2, w2hi, w2lo, 55296, 1);
    prep_k<<<54, 256>>>(qkv_w, qwhi, qwlo, 13824, 0);
    prep_k<<<18, 256>>>(proj_w, pwhi, pwlo, 4608, 0);
    temb_k<<<dim3(16, 6), 32>>>(t_emb, wt, bt, film);
    conv3x3_wino_k<<<cgrid, 256, WINO_SMEM>>>(x, w1hi, w1lo, b1, buf1, part0);
    gn_finalize_k<<<1, 64>>>(part0, 128, 8192, stats + 0*128);
    apply1_k<<<dim3(64, 8), 256>>>(buf1, stats + 0*128, g1, be1, film, buf2, part1);
    gn_finalize_k<<<1, 64>>>(part1, 8, 512, stats + 1*128);
    qkv_mma_k<<<dim3(128, 3, 16), 256, QKV_SMEM>>>(buf2, stats + 1*128, ga, ba,
                                                   qwhi, qwlo, qkv_b, qkvb);
    attn_core_k<<<dim3(256, 16, 2), 256, ATTN_SMEM>>>(qkvb, buf1, buf4);
    proj_mma_k<<<cgrid, 256, QKV_SMEM>>>(buf1, buf4, buf2, pwhi, pwlo,
                                         proj_b, buf3);
    conv3x3_wino_k<<<cgrid, 256, WINO_SMEM>>>(buf3, w2hi, w2lo, b2, buf1, part2);
    gn_finalize_k<<<1, 64>>>(part2, 128, 8192, stats + 2*128);
    apply3_k<<<NPIX/4/256, 256>>>(buf1, stats + 2*128, g2, be2, out);
}

// round 14
// speedup vs baseline: 1.2793x; 1.2793x over previous
#include <cuda_runtime.h>
#include <cuda_fp16.h>
#include <math.h>
#include <stdint.h>

#define NPIX (16*96*16384)
#define GN_N 393216

// ---------------- scratch ----------------------------------------------------
__device__ float g_buf1[NPIX];
__device__ float g_buf2[NPIX];
__device__ float g_buf3[NPIX];
__device__ float g_buf4[NPIX];
__device__ float g_qkv[3*NPIX];
__device__ float g_part0[16384];
__device__ float g_part1[1024];
__device__ float g_part2[16384];
__device__ float g_stats[3*64*2];
__device__ float g_film[16*192];
// fp16 split weights: hi = f16(w), lo = f16(w - hi); pair-packed per k2
__device__ uint32_t g_w1hi[41472], g_w1lo[41472];
__device__ uint32_t g_w2hi[41472], g_w2lo[41472];
__device__ uint32_t g_qwhi[13824], g_qwlo[13824];
__device__ uint32_t g_pwhi[4608],  g_pwlo[4608];

// ---------------- helpers ----------------------------------------------------
__device__ __forceinline__ uint32_t smem_u32(const void* p) {
    uint32_t a;
    asm("{ .reg .u64 t; cvta.to.shared.u64 t, %1; cvt.u32.u64 %0, t; }"
        : "=r"(a) : "l"(p));
    return a;
}
__device__ __forceinline__ void mma16816(float* c, const uint32_t* a,
                                         const uint32_t* b) {
    asm volatile(
        "mma.sync.aligned.m16n8k16.row.col.f32.f16.f16.f32 "
        "{%0,%1,%2,%3}, {%4,%5,%6,%7}, {%8,%9}, {%0,%1,%2,%3};"
        : "+f"(c[0]), "+f"(c[1]), "+f"(c[2]), "+f"(c[3])
        : "r"(a[0]), "r"(a[1]), "r"(a[2]), "r"(a[3]), "r"(b[0]), "r"(b[1]));
}
__device__ __forceinline__ void ldsm4(uint32_t* r, uint32_t a) {
    asm volatile("ldmatrix.sync.aligned.m8n8.x4.shared.b16 {%0,%1,%2,%3}, [%4];"
        : "=r"(r[0]), "=r"(r[1]), "=r"(r[2]), "=r"(r[3]) : "r"(a));
}
__device__ __forceinline__ unsigned short h16(float v) {
    return __half_as_ushort(__float2half_rn(v));
}

// ---------------- weight prepack (fp16 hi/lo) --------------------------------
__global__ __launch_bounds__(256) void prep_k(
    const float* __restrict__ wsrc, uint32_t* __restrict__ dh,
    uint32_t* __restrict__ dl, int n, int is33)
{
    int i = blockIdx.x*256 + threadIdx.x;
    if (i >= n) return;
    float v0, v1;
    if (is33) {
        int kk = i / 4608, r = i - kk*4608;
        int co = r / 48, k2 = r - co*48, ci = k2 << 1;
        v0 = wsrc[(co*96 + ci)*9 + kk];
        v1 = wsrc[(co*96 + ci + 1)*9 + kk];
    } else {
        int co = i / 48, k2 = i - co*48, ci = k2 << 1;
        v0 = wsrc[co*96 + ci];
        v1 = wsrc[co*96 + ci + 1];
    }
    __half h0 = __float2half_rn(v0);
    __half h1 = __float2half_rn(v1);
    __half l0 = __float2half_rn(v0 - __half2float(h0));
    __half l1 = __float2half_rn(v1 - __half2float(h1));
    dh[i] = (uint32_t)__half_as_ushort(h0) | ((uint32_t)__half_as_ushort(h1) << 16);
    dl[i] = (uint32_t)__half_as_ushort(l0) | ((uint32_t)__half_as_ushort(l1) << 16);
}

// ---------------- conv3x3: fp16 A-single / B-split, mma.sync -----------------
#define PS  104
#define PS2 208
#define C_A    0                     // u16 sA [130 x 104]     27,072 B
#define C_BH   27072                 // u32 Bhi [96 x 52]      19,968 B
#define C_BL   47040                 // u32 Blo                19,968 B
#define C_BIAS 67008
#define CONV_SMEM 67392

__global__ __launch_bounds__(256) void conv3x3_mma_k(
    const float* __restrict__ in, const uint32_t* __restrict__ wphi,
    const uint32_t* __restrict__ wplo,
    const float* __restrict__ bias, float* __restrict__ out,
    float* __restrict__ part)
{
    extern __shared__ char smem[];
    uint32_t sb = smem_u32(smem);
    unsigned short* sA = (unsigned short*)(smem + C_A);
    uint32_t* sBhi = (uint32_t*)(smem + C_BH);
    uint32_t* sBlo = (uint32_t*)(smem + C_BL);
    float*    sbias = (float*)(smem + C_BIAS);

    int tid = threadIdx.x, wid = tid >> 5, lane = tid & 31;
    int gid = lane >> 2, tig = lane & 3;
    int h = blockIdx.x, b = blockIdx.y;
    int m0 = (wid & 3) * 32;
    int n0 = (wid >> 2) * 48;

    float acc[12][4];
#pragma unroll
    for (int t = 0; t < 12; t++)
#pragma unroll
        for (int r = 0; r < 4; r++) acc[t][r] = 0.f;

    for (int i = tid; i < 96; i += 256) sbias[i] = bias[i];

    uint32_t aB = sb + C_A + (uint32_t)((((m0 + (lane & 15))*PS) + ((lane >> 4) << 3)) << 1);

    for (int ky = 0; ky < 3; ky++) {
        int gh = h + ky - 1;
        __syncthreads();
        for (int i = tid; i < 12480; i += 256) {
            int ci = i / 130, col = i - ci*130;
            int gw = col - 1;
            float v = 0.f;
            if ((unsigned)gh < 128u && (unsigned)gw < 128u)
                v = in[(((size_t)(b*96 + ci)) << 14) + (gh << 7) + gw];
            sA[col*PS + ci] = h16(v);
        }

        for (int kx = 0; kx < 3; kx++) {
            __syncthreads();
            int kk = ky*3 + kx;
            for (int i4 = tid; i4 < 1152; i4 += 256) {
                int co = i4 / 12, k2 = (i4 - co*12) << 2;
                uint4 vh = *(const uint4*)&wphi[kk*4608 + co*48 + k2];
                uint4 vl = *(const uint4*)&wplo[kk*4608 + co*48 + k2];
                *(uint4*)&sBhi[co*52 + k2] = vh;
                *(uint4*)&sBlo[co*52 + k2] = vl;
            }
            __syncthreads();

            uint32_t aox = (uint32_t)(kx*PS2);
#pragma unroll
            for (int kc = 0; kc < 6; kc++) {
                uint32_t a0[4], a1[4];
                ldsm4(a0, aB + aox + kc*32);
                ldsm4(a1, aB + aox + 16*PS2 + kc*32);
                uint32_t bhi[12], blo[12];
#pragma unroll
                for (int nt = 0; nt < 6; nt++) {
                    int co = n0 + nt*8 + gid;
                    int k2 = (kc << 3) + tig;
                    bhi[nt*2]   = sBhi[co*52 + k2];
                    bhi[nt*2+1] = sBhi[co*52 + k2 + 4];
                    blo[nt*2]   = sBlo[co*52 + k2];
                    blo[nt*2+1] = sBlo[co*52 + k2 + 4];
                }
#pragma unroll
                for (int nt = 0; nt < 6; nt++) {
                    mma16816(acc[nt],     a0, &bhi[nt*2]);
                    mma16816(acc[nt],     a0, &blo[nt*2]);
                    mma16816(acc[6 + nt], a1, &bhi[nt*2]);
                    mma16816(acc[6 + nt], a1, &blo[nt*2]);
                }
            }
        }
    }

    // epilogue: stores + per-group GN partials
    size_t obase = (((size_t)(b*96)) << 14) + (h << 7);
    float gs[2] = {0.f, 0.f}, gq[2] = {0.f, 0.f};
#pragma unroll
    for (int mt = 0; mt < 2; mt++) {
        int p = m0 + mt*16 + gid;
#pragma unroll
        for (int nt = 0; nt < 6; nt++) {
            int co = n0 + nt*8 + (tig << 1);
            float* c = acc[mt*6 + nt];
            float bs0 = sbias[co], bs1 = sbias[co+1];
            float v0 = c[0]+bs0, v1 = c[1]+bs1, v2 = c[2]+bs0, v3 = c[3]+bs1;
            out[obase + (((size_t)co)   << 14) + p]     = v0;
            out[obase + (((size_t)co+1) << 14) + p]     = v1;
            out[obase + (((size_t)co)   << 14) + p + 8] = v2;
            out[obase + (((size_t)co+1) << 14) + p + 8] = v3;
            int lg = nt / 3;
            gs[lg] += v0 + v1 + v2 + v3;
            gq[lg] += v0*v0 + v1*v1 + v2*v2 + v3*v3;
        }
    }
    __syncthreads();
    float* redS = (float*)(smem + C_BH);
    float* redQ = redS + 1024;
    int gb = (wid >> 2) * 2;
#pragma unroll
    for (int g = 0; g < 4; g++) {
        redS[g*256 + tid] = (g == gb) ? gs[0] : ((g == gb+1) ? gs[1] : 0.f);
        redQ[g*256 + tid] = (g == gb) ? gq[0] : ((g == gb+1) ? gq[1] : 0.f);
    }
    __syncthreads();
    for (int st = 128; st > 0; st >>= 1) {
        if (tid < st) {
#pragma unroll
            for (int g = 0; g < 4; g++) {
                redS[g*256 + tid] += redS[g*256 + tid + st];
                redQ[g*256 + tid] += redQ[g*256 + tid + st];
            }
        }
        __syncthreads();
    }
    if (tid < 4) {
        part[(b*4 + tid)*128 + h]        = redS[tid*256];
        part[8192 + (b*4 + tid)*128 + h] = redQ[tid*256];
    }
}

// ---------------- qkv 1x1: fp16 A-single / B-split (GN2 fused) ---------------
#define Q_A    0                     // u16 sA [128 x 104]     26,624 B
#define Q_BH   26624
#define Q_BL   46592
#define Q_BIAS 66560
#define QKV_SMEM 66944

__global__ __launch_bounds__(256) void qkv_mma_k(
    const float* __restrict__ R, const float* __restrict__ stats,
    const float* __restrict__ ga, const float* __restrict__ ba,
    const uint32_t* __restrict__ qwhi, const uint32_t* __restrict__ qwlo,
    const float* __restrict__ qb, float* __restrict__ out)
{
    extern __shared__ char smem[];
    uint32_t sb = smem_u32(smem);
    unsigned short* sA = (unsigned short*)(smem + Q_A);
    uint32_t* sBhi = (uint32_t*)(smem + Q_BH);
    uint32_t* sBlo = (uint32_t*)(smem + Q_BL);
    float*    sbias = (float*)(smem + Q_BIAS);

    int tid = threadIdx.x, wid = tid >> 5, lane = tid & 31;
    int gid = lane >> 2, tig = lane & 3;
    int h = blockIdx.x, cog = blockIdx.y, b = blockIdx.z;
    int m0 = (wid & 3) * 32;
    int n0 = (wid >> 2) * 48;

    float acc[12][4];
#pragma unroll
    for (int t = 0; t < 12; t++)
#pragma unroll
        for (int r = 0; r < 4; r++) acc[t][r] = 0.f;

    for (int i = tid; i < 12288; i += 256) {
        int ci = i >> 7, col = i & 127;
        int bg = b*4 + ci/24;
        float v = R[(((size_t)(b*96 + ci)) << 14) + (h << 7) + col];
        float xn = (v - stats[bg*2])*stats[bg*2+1]*ga[ci] + ba[ci];
        sA[col*PS + ci] = h16(xn);
    }
    for (int i4 = tid; i4 < 1152; i4 += 256) {
        int co = i4 / 12, k2 = (i4 - co*12) << 2;
        uint4 vh = *(const uint4*)&qwhi[cog*4608 + co*48 + k2];
        uint4 vl = *(const uint4*)&qwlo[cog*4608 + co*48 + k2];
        *(uint4*)&sBhi[co*52 + k2] = vh;
        *(uint4*)&sBlo[co*52 + k2] = vl;
    }
    for (int i = tid; i < 96; i += 256) sbias[i] = qb[cog*96 + i];
    __syncthreads();

    uint32_t aB = sb + Q_A + (uint32_t)((((m0 + (lane & 15))*PS) + ((lane >> 4) << 3)) << 1);

#pragma unroll
    for (int kc = 0; kc < 6; kc++) {
        uint32_t a0[4], a1[4];
        ldsm4(a0, aB + kc*32);
        ldsm4(a1, aB + 16*PS2 + kc*32);
        uint32_t bhi[12], blo[12];
#pragma unroll
        for (int nt = 0; nt < 6; nt++) {
            int co = n0 + nt*8 + gid;
            int k2 = (kc << 3) + tig;
            bhi[nt*2]   = sBhi[co*52 + k2];
            bhi[nt*2+1] = sBhi[co*52 + k2 + 4];
            blo[nt*2]   = sBlo[co*52 + k2];
            blo[nt*2+1] = sBlo[co*52 + k2 + 4];
        }
#pragma unroll
        for (int nt = 0; nt < 6; nt++) {
            mma16816(acc[nt],     a0, &bhi[nt*2]);
            mma16816(acc[nt],     a0, &blo[nt*2]);
            mma16816(acc[6 + nt], a1, &bhi[nt*2]);
            mma16816(acc[6 + nt], a1, &blo[nt*2]);
        }
    }

    size_t obase = (((size_t)(b*288 + cog*96)) << 14) + (h << 7);
#pragma unroll
    for (int mt = 0; mt < 2; mt++) {
        int p = m0 + mt*16 + gid;
#pragma unroll
        for (int nt = 0; nt < 6; nt++) {
            int co = n0 + nt*8 + (tig << 1);
            float* c = acc[mt*6 + nt];
            float bs0 = sbias[co], bs1 = sbias[co+1];
            out[obase + (((size_t)co)   << 14) + p]     = c[0] + bs0;
            out[obase + (((size_t)co+1) << 14) + p]     = c[1] + bs1;
            out[obase + (((size_t)co)   << 14) + p + 8] = c[2] + bs0;
            out[obase + (((size_t)co+1) << 14) + p + 8] = c[3] + bs1;
        }
    }
}

// ---------------- proj 1x1: fp16 + residual ----------------------------------
__global__ __launch_bounds__(256) void proj_mma_k(
    const float* __restrict__ o0, const float* __restrict__ o1,
    const float* __restrict__ R,
    const uint32_t* __restrict__ pwhi, const uint32_t* __restrict__ pwlo,
    const float* __restrict__ pb, float* __restrict__ A)
{
    extern __shared__ char smem[];
    uint32_t sb = smem_u32(smem);
    unsigned short* sA = (unsigned short*)(smem + Q_A);
    uint32_t* sBhi = (uint32_t*)(smem + Q_BH);
    uint32_t* sBlo = (uint32_t*)(smem + Q_BL);
    float*    sbias = (float*)(smem + Q_BIAS);

    int tid = threadIdx.x, wid = tid >> 5, lane = tid & 31;
    int gid = lane >> 2, tig = lane & 3;
    int h = blockIdx.x, b = blockIdx.y;
    int m0 = (wid & 3) * 32;
    int n0 = (wid >> 2) * 48;

    float acc[12][4];
#pragma unroll
    for (int t = 0; t < 12; t++)
#pragma unroll
        for (int r = 0; r < 4; r++) acc[t][r] = 0.f;

    for (int i = tid; i < 12288; i += 256) {
        int ci = i >> 7, col = i & 127;
        size_t idx = (((size_t)(b*96 + ci)) << 14) + (h << 7) + col;
        sA[col*PS + ci] = h16(o0[idx] + o1[idx]);
    }
    for (int i4 = tid; i4 < 1152; i4 += 256) {
        int co = i4 / 12, k2 = (i4 - co*12) << 2;
        uint4 vh = *(const uint4*)&pwhi[co*48 + k2];
        uint4 vl = *(const uint4*)&pwlo[co*48 + k2];
        *(uint4*)&sBhi[co*52 + k2] = vh;
        *(uint4*)&sBlo[co*52 + k2] = vl;
    }
    for (int i = tid; i < 96; i += 256) sbias[i] = pb[i];
    __syncthreads();

    uint32_t aB = sb + Q_A + (uint32_t)((((m0 + (lane & 15))*PS) + ((lane >> 4) << 3)) << 1);

#pragma unroll
    for (int kc = 0; kc < 6; kc++) {
        uint32_t a0[4], a1[4];
        ldsm4(a0, aB + kc*32);
        ldsm4(a1, aB + 16*PS2 + kc*32);
        uint32_t bhi[12], blo[12];
#pragma unroll
        for (int nt = 0; nt < 6; nt++) {
            int co = n0 + nt*8 + gid;
            int k2 = (kc << 3) + tig;
            bhi[nt*2]   = sBhi[co*52 + k2];
            bhi[nt*2+1] = sBhi[co*52 + k2 + 4];
            blo[nt*2]   = sBlo[co*52 + k2];
            blo[nt*2+1] = sBlo[co*52 + k2 + 4];
        }
#pragma unroll
        for (int nt = 0; nt < 6; nt++) {
            mma16816(acc[nt],     a0, &bhi[nt*2]);
            mma16816(acc[nt],     a0, &blo[nt*2]);
            mma16816(acc[6 + nt], a1, &bhi[nt*2]);
            mma16816(acc[6 + nt], a1, &blo[nt*2]);
        }
    }

    size_t obase = (((size_t)(b*96)) << 14) + (h << 7);
#pragma unroll
    for (int mt = 0; mt < 2; mt++) {
        int p = m0 + mt*16 + gid;
#pragma unroll
        for (int nt = 0; nt < 6; nt++) {
            int co = n0 + nt*8 + (tig << 1);
            float* c = acc[mt*6 + nt];
            float bs0 = sbias[co], bs1 = sbias[co+1];
            size_t i00 = obase + (((size_t)co) << 14) + p;
            size_t i10 = obase + (((size_t)co+1) << 14) + p;
            A[i00]     = R[i00]     + 0.5f*c[0] + bs0;
            A[i10]     = R[i10]     + 0.5f*c[1] + bs1;
            A[i00 + 8] = R[i00 + 8] + 0.5f*c[2] + bs0;
            A[i10 + 8] = R[i10 + 8] + 0.5f*c[3] + bs1;
        }
    }
}

// ---------------- GN finalize ------------------------------------------------
__global__ void gn_finalize_k(const float* __restrict__ part, int nch, int sqoff,
                              float* __restrict__ stats)
{
    int bg = threadIdx.x;
    float s = 0, q = 0;
    for (int c = 0; c < nch; c++) {
        s += part[bg*nch + c];
        q += part[sqoff + bg*nch + c];
    }
    float mean = s * (1.f/393216.f);
    float var  = q * (1.f/393216.f) - mean*mean;
    stats[bg*2 + 0] = mean;
    stats[bg*2 + 1] = rsqrtf(var + 1e-5f);
}

// ---------------- time-embedding MLP -----------------------------------------
__global__ void temb_k(const float* __restrict__ te, const float* __restrict__ wt,
                       const float* __restrict__ bt, float* __restrict__ film)
{
    __shared__ float sh[256];
    int b = blockIdx.x, j = blockIdx.y*32 + threadIdx.x;
    for (int i = threadIdx.x; i < 256; i += 32) sh[i] = te[b*256 + i];
    __syncthreads();
    const float* wr = wt + j*256;
    float s = bt[j];
#pragma unroll 4
    for (int k = 0; k < 256; k++) s += sh[k]*wr[k];
    s = s / (1.f + expf(-s));
    film[b*192 + j] = s;
}

// ---------------- apply GN1+SiLU+FiLM, emit GN2 partials ---------------------
__global__ __launch_bounds__(256) void apply1_k(
    const float* __restrict__ x, const float* __restrict__ stats,
    const float* __restrict__ g1, const float* __restrict__ be1,
    const float* __restrict__ film, float* __restrict__ out,
    float* __restrict__ part)
{
    int bg = blockIdx.x, chunk = blockIdx.y;
    int b = bg >> 2, g = bg & 3;
    int tid = threadIdx.x;
    size_t base = (size_t)bg*GN_N + (size_t)chunk*49152;
    float mean = stats[bg*2], rstd = stats[bg*2+1];
    const float4* xp = (const float4*)(x + base);
    float4* op = (float4*)(out + base);

    float sx=0, sy=0, sz=0, sw=0, qx=0, qy=0, qz=0, qw=0;
    for (int i = tid; i < 12288; i += 256) {
        int c = g*24 + chunk*3 + (i >> 12);
        float gam = g1[c]*rstd;
        float bet = be1[c] - mean*gam;
        float shf = 1.f + film[b*192 + c];
        float bia = film[b*192 + 96 + c];
        float4 v = xp[i];
        float t;
        t = v.x*gam + bet; t = t/(1.f+expf(-t)); v.x = t*shf + bia;
        t = v.y*gam + bet; t = t/(1.f+expf(-t)); v.y = t*shf + bia;
        t = v.z*gam + bet; t = t/(1.f+expf(-t)); v.z = t*shf + bia;
        t = v.w*gam + bet; t = t/(1.f+expf(-t)); v.w = t*shf + bia;
        op[i] = v;
        sx += v.x; sy += v.y; sz += v.z; sw += v.w;
        qx += v.x*v.x; qy += v.y*v.y; qz += v.z*v.z; qw += v.w*v.w;
    }
    __shared__ double sh[512];
    sh[tid]       = (double)sx + sy + sz + sw;
    sh[256 + tid] = (double)qx + qy + qz + qw;
    __syncthreads();
    for (int st = 128; st > 0; st >>= 1) {
        if (tid < st) { sh[tid] += sh[tid+st]; sh[256+tid] += sh[256+tid+st]; }
        __syncthreads();
    }
    if (tid == 0) {
        part[bg*8 + chunk]       = (float)sh[0];
        part[512 + bg*8 + chunk] = (float)sh[256];
    }
}

// ---------------- final: SiLU(GN(conv2)) -> d_out ----------------------------
__global__ __launch_bounds__(256) void apply3_k(
    const float* __restrict__ x, const float* __restrict__ stats,
    const float* __restrict__ g2, const float* __restrict__ be2,
    float* __restrict__ out)
{
    int idx4 = blockIdx.x*256 + threadIdx.x;
    if (idx4 >= NPIX/4) return;
    int flat = idx4 << 2;
    int cimg = flat >> 14;
    int b = cimg / 96, c = cimg - 96*b;
    int bg = b*4 + c/24;
    float mean = stats[bg*2], rstd = stats[bg*2+1];
    float gam = g2[c]*rstd;
    float bet = be2[c] - mean*gam;
    float4 v = *(const float4*)&x[flat];
    float t;
    t = v.x*gam + bet; v.x = t/(1.f+expf(-t));
    t = v.y*gam + bet; v.y = t/(1.f+expf(-t));
    t = v.z*gam + bet; v.z = t/(1.f+expf(-t));
    t = v.w*gam + bet; v.w = t/(1.f+expf(-t));
    *(float4*)&out[flat] = v;
}

// ---------------- attention core ---------------------------------------------
__global__ __launch_bounds__(256) void attn_core_k(
    const float* __restrict__ qkv, float* __restrict__ o0, float* __restrict__ o1)
{
    extern __shared__ float sm[];
    float* sq   = sm;
    float* slog = sq + 18432;
    float* spr  = slog + 576;

    int b = blockIdx.y, branch = blockIdx.z;
    int hn = blockIdx.x >> 4, wn = blockIdx.x & 15;
    int sh = branch*4;
    int h0 = hn*8 + sh, w0 = wn*8 + sh;
    int tid = threadIdx.x;

    for (int i = tid; i < 4608; i += 256) {
        int c = i >> 4, lq = i & 15, l = lq << 2;
        int gh = (h0 + (l >> 3)) & 127, gw = (w0 + (l & 7)) & 127;
        *(float4*)&sq[(c << 6) + l] =
            *(const float4*)&qkv[(((size_t)(b*288 + c)) << 14) + (gh << 7) + gw];
    }
    __syncthreads();

    const float scale = 0.40824829046386307f;
    for (int i = tid; i < 576; i += 256) {
        int head = i / 36, r = i - head*36, d = r / 6, e = r - d*6;
        const float* qp = &sq[(head*6 + d) << 6];
        const float* kp = &sq[(96 + head*6 + e) << 6];
        float a = 0.f;
#pragma unroll 8
        for (int l = 0; l < 64; l++) a += qp[l]*kp[l];
        slog[i] = a*scale;
    }
    __syncthreads();

    if (tid < 96) {
        int head = tid / 6, d = tid - head*6, base = head*36 + d*6;
        float m = -1e30f;
#pragma unroll
        for (int e = 0; e < 6; e++) m = fmaxf(m, slog[base+e]);
        float ex[6]; float s = 0.f;
#pragma unroll
        for (int e = 0; e < 6; e++) { ex[e] = expf(slog[base+e] - m); s += ex[e]; }
        float inv = 1.f/s;
#pragma unroll
        for (int e = 0; e < 6; e++) spr[base+e] = ex[e]*inv;
    }
    __syncthreads();

    float* o = branch ? o1 : o0;
    for (int i = tid; i < 1536; i += 256) {
        int ch = i >> 4, lq = i & 15, l = lq << 2;
        int head = ch / 6, d = ch - head*6;
        float4 a = {0.f, 0.f, 0.f, 0.f};
#pragma unroll
        for (int e = 0; e < 6; e++) {
            float p = spr[head*36 + d*6 + e];
            float4 vv = *(const float4*)&sq[((192 + head*6 + e) << 6) + l];
            a.x += p*vv.x; a.y += p*vv.y; a.z += p*vv.z; a.w += p*vv.w;
        }
        int gh = (h0 + (l >> 3)) & 127, gw = (w0 + (l & 7)) & 127;
        *(float4*)&o[(((size_t)(b*96 + ch)) << 14) + (gh << 7) + gw] = a;
    }
}

// ---------------- launch -----------------------------------------------------
extern "C" void kernel_launch(void* const* d_in, const int* in_sizes, int n_in,
                              void* d_out, int out_size)
{
    const float* x      = (const float*)d_in[0];
    const float* t_emb  = (const float*)d_in[1];
    const float* w1     = (const float*)d_in[2];
    const float* b1     = (const float*)d_in[3];
    const float* g1     = (const float*)d_in[4];
    const float* be1    = (const float*)d_in[5];
    const float* wt     = (const float*)d_in[6];
    const float* bt     = (const float*)d_in[7];
    const float* qkv_w  = (const float*)d_in[8];
    const float* qkv_b  = (const float*)d_in[9];
    const float* proj_w = (const float*)d_in[10];
    const float* proj_b = (const float*)d_in[11];
    const float* ga     = (const float*)d_in[12];
    const float* ba     = (const float*)d_in[13];
    const float* w2     = (const float*)d_in[14];
    const float* b2     = (const float*)d_in[15];
    const float* g2     = (const float*)d_in[16];
    const float* be2    = (const float*)d_in[17];
    float* out = (float*)d_out;

    float *buf1, *buf2, *buf3, *buf4, *qkvb, *part0, *part1, *part2, *stats, *film;
    uint32_t *w1hi, *w1lo, *w2hi, *w2lo, *qwhi, *qwlo, *pwhi, *pwlo;
    cudaGetSymbolAddress((void**)&buf1, g_buf1);
    cudaGetSymbolAddress((void**)&buf2, g_buf2);
    cudaGetSymbolAddress((void**)&buf3, g_buf3);
    cudaGetSymbolAddress((void**)&buf4, g_buf4);
    cudaGetSymbolAddress((void**)&qkvb, g_qkv);
    cudaGetSymbolAddress((void**)&part0, g_part0);
    cudaGetSymbolAddress((void**)&part1, g_part1);
    cudaGetSymbolAddress((void**)&part2, g_part2);
    cudaGetSymbolAddress((void**)&stats, g_stats);
    cudaGetSymbolAddress((void**)&film, g_film);
    cudaGetSymbolAddress((void**)&w1hi, g_w1hi);
    cudaGetSymbolAddress((void**)&w1lo, g_w1lo);
    cudaGetSymbolAddress((void**)&w2hi, g_w2hi);
    cudaGetSymbolAddress((void**)&w2lo, g_w2lo);
    cudaGetSymbolAddress((void**)&qwhi, g_qwhi);
    cudaGetSymbolAddress((void**)&qwlo, g_qwlo);
    cudaGetSymbolAddress((void**)&pwhi, g_pwhi);
    cudaGetSymbolAddress((void**)&pwlo, g_pwlo);

    const int ATTN_SMEM = (18432 + 576 + 576) * 4;
    cudaFuncSetAttribute(attn_core_k, cudaFuncAttributeMaxDynamicSharedMemorySize,
                         ATTN_SMEM);
    cudaFuncSetAttribute(conv3x3_mma_k, cudaFuncAttributeMaxDynamicSharedMemorySize,
                         CONV_SMEM);
    cudaFuncSetAttribute(qkv_mma_k, cudaFuncAttributeMaxDynamicSharedMemorySize,
                         QKV_SMEM);
    cudaFuncSetAttribute(proj_mma_k, cudaFuncAttributeMaxDynamicSharedMemorySize,
                         QKV_SMEM);

    dim3 cgrid(128, 16);

    prep_k<<<162, 256>>>(w1, w1hi, w1lo, 41472, 1);
    prep_k<<<162, 256>>>(w2, w2hi, w2lo, 41472, 1);
    prep_k<<<54, 256>>>(qkv_w, qwhi, qwlo, 13824, 0);
    prep_k<<<18, 256>>>(proj_w, pwhi, pwlo, 4608, 0);
    temb_k<<<dim3(16, 6), 32>>>(t_emb, wt, bt, film);
    conv3x3_mma_k<<<cgrid, 256, CONV_SMEM>>>(x, w1hi, w1lo, b1, buf1, part0);
    gn_finalize_k<<<1, 64>>>(part0, 128, 8192, stats + 0*128);
    apply1_k<<<dim3(64, 8), 256>>>(buf1, stats + 0*128, g1, be1, film, buf2, part1);
    gn_finalize_k<<<1, 64>>>(part1, 8, 512, stats + 1*128);
    qkv_mma_k<<<dim3(128, 3, 16), 256, QKV_SMEM>>>(buf2, stats + 1*128, ga, ba,
                                                   qwhi, qwlo, qkv_b, qkvb);
    attn_core_k<<<dim3(256, 16, 2), 256, ATTN_SMEM>>>(qkvb, buf1, buf4);
    proj_mma_k<<<cgrid, 256, QKV_SMEM>>>(buf1, buf4, buf2, pwhi, pwlo,
                                         proj_b, buf3);
    conv3x3_mma_k<<<cgrid, 256, CONV_SMEM>>>(buf3, w2hi, w2lo, b2, buf1, part2);
    gn_finalize_k<<<1, 64>>>(part2, 128, 8192, stats + 2*128);
    apply3_k<<<NPIX/4/256, 256>>>(buf1, stats + 2*128, g2, be2, out);
}